// round 10
// baseline (speedup 1.0000x reference)
#include <cuda_runtime.h>
#include <cuda_bf16.h>
#include <math.h>

#define MAXN 50000
#define MAXE 800000
#define F128 128

// ---------------- scratch (device globals; no allocation allowed) ----------
__device__ __align__(128) __nv_bfloat16 g_hsb[MAXN * F128];   // GEMM outputs (pre-agg), bf16
__device__ __align__(128) __nv_bfloat16 g_accb[MAXN * F128];  // agg1 out (post-tanh), bf16 -> gemm2
__device__ __align__(128) float g_accf[MAXN * F128];          // agg2 out (post-tanh), fp32 -> final
__device__ __align__(128) __nv_bfloat16 g_W1b[F128 * F128];   // W1 bf16, smem-swizzled layout
__device__ __align__(128) __nv_bfloat16 g_Wcb[F128 * F128];   // Wl@W2 bf16, smem-swizzled layout
__device__ float g_bpre[F128];
__device__ int   g_indeg[MAXN];
__device__ int   g_off[MAXN];
__device__ int   g_cur[MAXN];
__device__ int   g_csr[MAXE];
__device__ int   g_bsum[256];
__device__ int   g_bex[256];

// ---------------- helpers ----------------
__device__ __forceinline__ float4 f4add(float4 a, float4 b) {
    return make_float4(a.x + b.x, a.y + b.y, a.z + b.z, a.w + b.w);
}

__device__ __forceinline__ void atomicMaxFloat(float* addr, float v) {
    if (v >= 0.0f) atomicMax((int*)addr, __float_as_int(v));
    else           atomicMin((unsigned int*)addr, __float_as_uint(v));
}

// pack 2 floats -> bf16x2
__device__ __forceinline__ unsigned cvt_bf2(float hi, float lo) {
    unsigned d;
    asm("cvt.rn.bf16x2.f32 %0, %1, %2;" : "=r"(d) : "f"(hi), "f"(lo));
    return d;
}

__device__ __forceinline__ float4 b2f4(uint2 u) {
    __nv_bfloat162 p0 = *reinterpret_cast<__nv_bfloat162*>(&u.x);
    __nv_bfloat162 p1 = *reinterpret_cast<__nv_bfloat162*>(&u.y);
    float2 f0 = __bfloat1622float2(p0);
    float2 f1 = __bfloat1622float2(p1);
    return make_float4(f0.x, f0.y, f1.x, f1.y);
}

__device__ __forceinline__ unsigned sm_u32(const void* p) {
    return (unsigned)__cvta_generic_to_shared(p);
}

#define LDSM_X4(r0, r1, r2, r3, addr) \
    asm volatile("ldmatrix.sync.aligned.m8n8.x4.shared.b16 {%0,%1,%2,%3}, [%4];" \
        : "=r"(r0), "=r"(r1), "=r"(r2), "=r"(r3) : "r"(addr))
#define LDSM_X4T(r0, r1, r2, r3, addr) \
    asm volatile("ldmatrix.sync.aligned.m8n8.x4.trans.shared.b16 {%0,%1,%2,%3}, [%4];" \
        : "=r"(r0), "=r"(r1), "=r"(r2), "=r"(r3) : "r"(addr))

__device__ __forceinline__ void mma_bf16(float* c, const unsigned* a, const unsigned* b) {
    asm("mma.sync.aligned.m16n8k16.row.col.f32.bf16.bf16.f32 "
        "{%0,%1,%2,%3}, {%4,%5,%6,%7}, {%8,%9}, {%0,%1,%2,%3};"
        : "+f"(c[0]), "+f"(c[1]), "+f"(c[2]), "+f"(c[3])
        : "r"(a[0]), "r"(a[1]), "r"(a[2]), "r"(a[3]), "r"(b[0]), "r"(b[1]));
}

#define CP_ASYNC16(dst, src) \
    asm volatile("cp.async.cg.shared.global [%0], [%1], 16;" :: "r"(dst), "l"(src))
#define CP_COMMIT() asm volatile("cp.async.commit_group;")
#define CP_WAIT0()  asm volatile("cp.async.wait_group 0;" ::: "memory")

// packed fp32x2 FMA (k_final)
#define FMA2(d, a, b) \
    asm("fma.rn.f32x2 %0, %1, %2, %0;" : "+l"(d) : "l"(a), "l"(b))
#define PACK2(d, lo, hi) \
    asm("mov.b64 %0, {%1, %2};" : "=l"(d) : "r"(__float_as_uint(lo)), "r"(__float_as_uint(hi)))
#define UNPACK2(lo, hi, d) \
    { unsigned int _l, _h; asm("mov.b64 {%0, %1}, %2;" : "=r"(_l), "=r"(_h) : "l"(d)); \
      lo = __uint_as_float(_l); hi = __uint_as_float(_h); }

// ---------------- preprocessing ----------------
__global__ void k_init_indeg(int N) {
    int n = blockIdx.x * blockDim.x + threadIdx.x;
    if (n < N) g_indeg[n] = 0;
}

__global__ void k_count(const int* __restrict__ ei, int E) {
    int e = blockIdx.x * blockDim.x + threadIdx.x;
    if (e < E) atomicAdd(&g_indeg[ei[E + e]], 1);
}

__global__ void k_scan_p1(int N) {
    int t = threadIdx.x;
    int n = blockIdx.x * 256 + t;
    int v = (n < N) ? g_indeg[n] : 0;
    #pragma unroll
    for (int o = 16; o > 0; o >>= 1) v += __shfl_down_sync(0xffffffffu, v, o);
    __shared__ int ws[8];
    if ((t & 31) == 0) ws[t >> 5] = v;
    __syncthreads();
    if (t < 8) {
        int s = ws[t];
        #pragma unroll
        for (int o = 4; o > 0; o >>= 1) s += __shfl_down_sync(0xffu, s, o);
        if (t == 0) g_bsum[blockIdx.x] = s;
    }
}

__global__ void k_scan_p2(int NB) {
    int t = threadIdx.x;
    int lane = t & 31, w = t >> 5;
    int v = (t < NB) ? g_bsum[t] : 0;
    int x = v;
    #pragma unroll
    for (int o = 1; o < 32; o <<= 1) {
        int y = __shfl_up_sync(0xffffffffu, x, o);
        if (lane >= o) x += y;
    }
    __shared__ int ws[8];
    if (lane == 31) ws[w] = x;
    __syncthreads();
    int wo = 0;
    #pragma unroll
    for (int j = 0; j < 8; j++) if (j < w) wo += ws[j];
    g_bex[t] = x - v + wo;
}

__global__ void k_scan_p3(int N) {
    int t = threadIdx.x;
    int n = blockIdx.x * 256 + t;
    int lane = t & 31, w = t >> 5;
    int deg = (n < N) ? g_indeg[n] : 0;
    int x = deg;
    #pragma unroll
    for (int o = 1; o < 32; o <<= 1) {
        int y = __shfl_up_sync(0xffffffffu, x, o);
        if (lane >= o) x += y;
    }
    __shared__ int ws[8];
    if (lane == 31) ws[w] = x;
    __syncthreads();
    int wo = 0;
    #pragma unroll
    for (int j = 0; j < 8; j++) if (j < w) wo += ws[j];
    int ex = x - deg + wo + g_bex[blockIdx.x];
    if (n < N) { g_off[n] = ex; g_cur[n] = ex; }
}

__global__ void k_fill(const int* __restrict__ ei, int E) {
    int e = blockIdx.x * blockDim.x + threadIdx.x;
    if (e < E) {
        int src = ei[e];
        int dst = ei[E + e];
        int p = atomicAdd(&g_cur[dst], 1);
        g_csr[p] = src;
    }
}

// ------- weight prep: Wc=Wl@W2 -> bf16 swizzled; W1 -> bf16 swizzled; bpre; out init
__device__ __forceinline__ void store_swz(__nv_bfloat16* base, int k, int c, float v) {
    int idx = k * 128 + ((((c >> 3) ^ (k & 7)) << 3) | (c & 7));
    base[idx] = __float2bfloat16(v);
}

__global__ void k_wc(const float* __restrict__ Wl, const float* __restrict__ bl,
                     const float* __restrict__ W2, const float* __restrict__ W1,
                     float* __restrict__ out) {
    int idx = blockIdx.x * blockDim.x + threadIdx.x;
    if (idx < F128 * F128) {
        int r = idx >> 7, c = idx & 127;
        float s = 0.0f;
        #pragma unroll 8
        for (int k = 0; k < F128; k++) s += Wl[r * F128 + k] * W2[k * F128 + c];
        store_swz(g_Wcb, r, c, s);
        store_swz(g_W1b, r, c, W1[idx]);
    }
    if (idx < F128) {
        float s = 0.0f;
        #pragma unroll 8
        for (int k = 0; k < F128; k++) s += bl[k] * W2[k * F128 + idx];
        g_bpre[idx] = s;
    }
    if (idx < 64) out[idx] = -INFINITY;
}

// ============== bf16 MMA GEMM: 128(M)x128(N)xK128, 8 warps =================
// sA: bf16 [m=128][k chunks], pitch 256B, chunk c ^ (m&7)
// sB: bf16 [k=128][n chunks], pitch 256B, chunk c ^ (k&7) (pre-swizzled in gmem)
// Warp w: wm=w&1 -> rows wm*64..+63 (4 m16 tiles); wn=w>>1 -> cols wn*32..+31

__device__ __forceinline__ void mma_loop128(const char* sA, const char* sB,
                                            int lane, int wm, int wn, float c[4][4][4]) {
    int tl = lane >> 3, li = lane & 7;
    unsigned aBase = sm_u32(sA) + (unsigned)((wm * 64 + li + (tl & 1) * 8) * 256);
    int thA = tl >> 1;
    int klB = li + (tl & 1) * 8;
    int nch0 = wn * 4 + (tl >> 1);
    unsigned bBase0 = sm_u32(sB) + (unsigned)(klB * 256 + ((nch0 ^ (klB & 7)) << 4));
    unsigned bBase1 = sm_u32(sB) + (unsigned)(klB * 256 + (((nch0 + 2) ^ (klB & 7)) << 4));
    #pragma unroll
    for (int s = 0; s < 8; s++) {
        unsigned a[4][4], b[4][2];
        unsigned ach = (unsigned)((((2 * s + thA) ^ li)) << 4);
        #pragma unroll
        for (int mt = 0; mt < 4; mt++)
            LDSM_X4(a[mt][0], a[mt][1], a[mt][2], a[mt][3],
                    aBase + (unsigned)(mt * 16 * 256) + ach);
        LDSM_X4T(b[0][0], b[0][1], b[1][0], b[1][1], bBase0 + (unsigned)(s * 4096));
        LDSM_X4T(b[2][0], b[2][1], b[3][0], b[3][1], bBase1 + (unsigned)(s * 4096));
        #pragma unroll
        for (int mt = 0; mt < 4; mt++)
            #pragma unroll
            for (int nt = 0; nt < 4; nt++)
                mma_bf16(c[mt][nt], a[mt], b[nt]);
    }
}

// ---------------- GEMM 1: hsb = bf16( (x @ W1) * dinv[row] ) ---------------
__global__ __launch_bounds__(256, 2) void k_gemm1(const float* __restrict__ A, int N) {
    extern __shared__ __align__(16) char smem[];
    char* sA = smem;
    char* sB = smem + 32768;
    int tid = threadIdx.x;
    int lane = tid & 31, w = tid >> 5;
    int wm = w & 1, wn = w >> 1;
    int q = lane >> 2, t = lane & 3;
    int row0 = blockIdx.x * 128;
    float c[4][4][4] = {};

    // stage B: raw 16B copies from pre-swizzled g_W1b
    {
        unsigned dst = sm_u32(sB) + (unsigned)(tid * 128);
        const char* src = (const char*)g_W1b + tid * 128;
        #pragma unroll
        for (int i = 0; i < 8; i++) CP_ASYNC16(dst + i * 16, src + i * 16);
        CP_COMMIT();
    }
    // stage A: fp32 -> bf16 swizzled
    {
        int m = tid & 127, hb = (tid >> 7) * 8;
        int gr = row0 + m;
        const float4* Ar = (const float4*)(A + gr * 128 + hb * 8);
        #pragma unroll
        for (int ch = 0; ch < 8; ch++) {
            float4 v0 = make_float4(0, 0, 0, 0), v1 = make_float4(0, 0, 0, 0);
            if (gr < N) { v0 = Ar[ch * 2]; v1 = Ar[ch * 2 + 1]; }
            uint4 u;
            u.x = cvt_bf2(v0.y, v0.x); u.y = cvt_bf2(v0.w, v0.z);
            u.z = cvt_bf2(v1.y, v1.x); u.w = cvt_bf2(v1.w, v1.z);
            *(uint4*)(sA + m * 256 + (((hb + ch) ^ (m & 7)) << 4)) = u;
        }
    }
    CP_WAIT0();
    __syncthreads();

    mma_loop128(sA, sB, lane, wm, wn, c);

    #pragma unroll
    for (int mt = 0; mt < 4; mt++) {
        #pragma unroll
        for (int half = 0; half < 2; half++) {
            int r = row0 + wm * 64 + mt * 16 + q + half * 8;
            if (r < N) {
                float dv = rsqrtf((float)(g_indeg[r] + 1));
                #pragma unroll
                for (int nt = 0; nt < 4; nt++) {
                    int col = wn * 32 + nt * 8 + 2 * t;
                    *(unsigned*)(&g_hsb[r * 128 + col]) =
                        cvt_bf2(c[mt][nt][half * 2 + 1] * dv, c[mt][nt][half * 2] * dv);
                }
            }
        }
    }
}

// ------- GEMM 2: hsb = bf16( (accb @ Wc + bpre) * dinv )  (A already tanh'd)
__global__ __launch_bounds__(256, 2) void k_gemm2(int N) {
    extern __shared__ __align__(16) char smem[];
    char* sA = smem;
    char* sB = smem + 32768;
    int tid = threadIdx.x;
    int lane = tid & 31, w = tid >> 5;
    int wm = w & 1, wn = w >> 1;
    int q = lane >> 2, t = lane & 3;
    int row0 = blockIdx.x * 128;
    float c[4][4][4] = {};

    {
        unsigned dst = sm_u32(sB) + (unsigned)(tid * 128);
        const char* src = (const char*)g_Wcb + tid * 128;
        #pragma unroll
        for (int i = 0; i < 8; i++) CP_ASYNC16(dst + i * 16, src + i * 16);
    }
    // stage A: bf16 copy with swizzle (no math)
    {
        int m = tid & 127, hb = (tid >> 7) * 8;
        int gr = row0 + m;
        unsigned drow = sm_u32(sA) + (unsigned)(m * 256);
        if (gr < N) {
            const char* src = (const char*)g_accb + (gr * 128 + hb * 8) * 2;
            #pragma unroll
            for (int ch = 0; ch < 8; ch++)
                CP_ASYNC16(drow + (((hb + ch) ^ (m & 7)) << 4), src + ch * 16);
        } else {
            uint4 z = make_uint4(0, 0, 0, 0);
            #pragma unroll
            for (int ch = 0; ch < 8; ch++)
                *(uint4*)(sA + m * 256 + (((hb + ch) ^ (m & 7)) << 4)) = z;
        }
    }
    CP_COMMIT();
    CP_WAIT0();
    __syncthreads();

    mma_loop128(sA, sB, lane, wm, wn, c);

    #pragma unroll
    for (int mt = 0; mt < 4; mt++) {
        #pragma unroll
        for (int half = 0; half < 2; half++) {
            int r = row0 + wm * 64 + mt * 16 + q + half * 8;
            if (r < N) {
                float dv = rsqrtf((float)(g_indeg[r] + 1));
                #pragma unroll
                for (int nt = 0; nt < 4; nt++) {
                    int col = wn * 32 + nt * 8 + 2 * t;
                    float2 bp = *(const float2*)(g_bpre + col);
                    *(unsigned*)(&g_hsb[r * 128 + col]) =
                        cvt_bf2((c[mt][nt][half * 2 + 1] + bp.y) * dv,
                                (c[mt][nt][half * 2] + bp.x) * dv);
                }
            }
        }
    }
}

// -------- Aggregation + fused epilogue (fp32 tanh):
//   out[n] = tanh( dinv[n] * (hsb[n] + sum_{in} hsb[src]) + bias )
// WRITE_F32=false -> bf16 g_accb (feeds bf16-MMA gemm2; quantized there anyway)
// WRITE_F32=true  -> fp32 g_accf (feeds fp32 final GEMM; keeps last layer exact)
template <bool WRITE_F32>
__global__ void k_agg(const float* __restrict__ bias, int N) {
    int gw = (blockIdx.x * blockDim.x + threadIdx.x) >> 5;
    int lane = threadIdx.x & 31;
    if (gw >= N) return;
    const uint2* hsb = (const uint2*)g_hsb;
    int beg = g_off[gw];
    int cnt = g_indeg[gw];
    float4 s = b2f4(hsb[gw * 32 + lane]);
    int j = 0;
    for (; j + 4 <= cnt; j += 4) {
        int s0 = g_csr[beg + j];
        int s1 = g_csr[beg + j + 1];
        int s2 = g_csr[beg + j + 2];
        int s3 = g_csr[beg + j + 3];
        float4 a = b2f4(hsb[s0 * 32 + lane]);
        float4 b = b2f4(hsb[s1 * 32 + lane]);
        float4 c = b2f4(hsb[s2 * 32 + lane]);
        float4 d = b2f4(hsb[s3 * 32 + lane]);
        s = f4add(s, f4add(f4add(a, b), f4add(c, d)));
    }
    for (; j < cnt; j++) s = f4add(s, b2f4(hsb[g_csr[beg + j] * 32 + lane]));
    float dv = rsqrtf((float)(cnt + 1));
    float4 bb = *(const float4*)(bias + lane * 4);
    float z0 = tanhf(fmaf(dv, s.x, bb.x));
    float z1 = tanhf(fmaf(dv, s.y, bb.y));
    float z2 = tanhf(fmaf(dv, s.z, bb.z));
    float z3 = tanhf(fmaf(dv, s.w, bb.w));
    if (WRITE_F32) {
        ((float4*)g_accf)[gw * 32 + lane] = make_float4(z0, z1, z2, z3);
    } else {
        ((uint2*)g_accb)[gw * 32 + lane] = make_uint2(cvt_bf2(z1, z0), cvt_bf2(z3, z2));
    }
}

// ---------------- Final: out = max_n( accf @ Wo + bo )  (fp32 FFMA2) -------
__global__ void k_final(const float* __restrict__ Wo, const float* __restrict__ bo,
                        float* __restrict__ out, int N) {
    __shared__ float As[32 * 64];
    __shared__ float Bs[32 * 64];
    int tid = threadIdx.x;
    int tc = tid & 31, tr = tid >> 5;
    int row0 = blockIdx.x * 64;
    unsigned long long acc2[4][2] = {};

    int lr = tid & 63;
    int kc = (tid >> 6) * 8;
    int gr = row0 + lr;

    for (int k0 = 0; k0 < 128; k0 += 32) {
        {
            float4 v0 = make_float4(0, 0, 0, 0), v1 = make_float4(0, 0, 0, 0);
            if (gr < N) {
                v0 = *(const float4*)(g_accf + gr * 128 + k0 + kc);
                v1 = *(const float4*)(g_accf + gr * 128 + k0 + kc + 4);
            }
            As[(kc + 0) * 64 + lr] = v0.x; As[(kc + 1) * 64 + lr] = v0.y;
            As[(kc + 2) * 64 + lr] = v0.z; As[(kc + 3) * 64 + lr] = v0.w;
            As[(kc + 4) * 64 + lr] = v1.x; As[(kc + 5) * 64 + lr] = v1.y;
            As[(kc + 6) * 64 + lr] = v1.z; As[(kc + 7) * 64 + lr] = v1.w;
        }
        {
            const float4* Bg = (const float4*)(Wo + k0 * 64);
            float4* Bs4 = (float4*)Bs;
            Bs4[tid] = Bg[tid];
            Bs4[tid + 256] = Bg[tid + 256];
        }
        __syncthreads();
        #pragma unroll
        for (int k = 0; k < 32; k++) {
            float2 b2v = *(const float2*)(Bs + k * 64 + tc * 2);
            unsigned long long bb[2];
            PACK2(bb[0], b2v.x, b2v.x); PACK2(bb[1], b2v.y, b2v.y);
            #pragma unroll
            for (int i2 = 0; i2 < 4; i2++) {
                unsigned long long ap = *(const unsigned long long*)(As + k * 64 + tr * 8 + 2 * i2);
                FMA2(acc2[i2][0], ap, bb[0]);
                FMA2(acc2[i2][1], ap, bb[1]);
            }
        }
        __syncthreads();
    }
    float bo0 = bo[tc * 2], bo1 = bo[tc * 2 + 1];
    float m0 = -INFINITY, m1 = -INFINITY;
    #pragma unroll
    for (int i2 = 0; i2 < 4; i2++) {
        float lo0, hi0, lo1, hi1;
        UNPACK2(lo0, hi0, acc2[i2][0]);
        UNPACK2(lo1, hi1, acc2[i2][1]);
        int r0 = row0 + tr * 8 + 2 * i2;
        if (r0 < N)     { m0 = fmaxf(m0, lo0 + bo0); m1 = fmaxf(m1, lo1 + bo1); }
        if (r0 + 1 < N) { m0 = fmaxf(m0, hi0 + bo0); m1 = fmaxf(m1, hi1 + bo1); }
    }
    As[tr * 64 + tc * 2] = m0;
    As[tr * 64 + tc * 2 + 1] = m1;
    __syncthreads();
    if (tid < 64) {
        float m = As[tid];
        #pragma unroll
        for (int j = 1; j < 8; j++) m = fmaxf(m, As[j * 64 + tid]);
        atomicMaxFloat(&out[tid], m);
    }
}

// ---------------- launch ----------------
extern "C" void kernel_launch(void* const* d_in, const int* in_sizes, int n_in,
                              void* d_out, int out_size) {
    const float* x  = (const float*)d_in[0];
    const int*   ei = (const int*)d_in[1];
    const float* W1 = (const float*)d_in[2];
    const float* b1 = (const float*)d_in[3];
    const float* Wl = (const float*)d_in[4];
    const float* bl = (const float*)d_in[5];
    const float* W2 = (const float*)d_in[6];
    const float* b2 = (const float*)d_in[7];
    const float* Wo = (const float*)d_in[8];
    const float* bo = (const float*)d_in[9];
    float* out = (float*)d_out;

    int N = in_sizes[0] / F128;   // 50000
    int E = in_sizes[1] / 2;      // 800000

    int nbN = (N + 255) / 256;
    int nbE = (E + 255) / 256;
    int nbG = (N + 127) / 128;    // 391 (MMA gemms)
    int nbF = (N + 63) / 64;      // 782 (final)
    int nbA = (N + 7) / 8;        // 6250

    static const int SMEM = 65536;
    cudaFuncSetAttribute(k_gemm1, cudaFuncAttributeMaxDynamicSharedMemorySize, SMEM);
    cudaFuncSetAttribute(k_gemm2, cudaFuncAttributeMaxDynamicSharedMemorySize, SMEM);

    // launch #4 = k_gemm1 (profiled by ncu)
    k_init_indeg<<<nbN, 256>>>(N);                       // 1
    k_wc<<<64, 256>>>(Wl, bl, W2, W1, out);              // 2
    k_count<<<nbE, 256>>>(ei, E);                        // 3
    k_gemm1<<<nbG, 256, SMEM>>>(x, N);                   // 4  <- profiled
    k_scan_p1<<<nbN, 256>>>(N);                          // 5
    k_scan_p2<<<1, 256>>>(nbN);                          // 6
    k_scan_p3<<<nbN, 256>>>(N);                          // 7
    k_fill<<<nbE, 256>>>(ei, E);                         // 8
    k_agg<false><<<nbA, 256>>>(b1, N);                   // 9   -> bf16 for gemm2
    k_gemm2<<<nbG, 256, SMEM>>>(N);                      // 10
    k_agg<true><<<nbA, 256>>>(b2, N);                    // 11  -> fp32 for final
    k_final<<<nbF, 256>>>(Wo, bo, out, N);               // 12
}

// round 11
// speedup vs baseline: 1.4848x; 1.4848x over previous
#include <cuda_runtime.h>
#include <cuda_bf16.h>
#include <math.h>

#define MAXN 50000
#define MAXE 800000
#define F128 128

// ---------------- scratch (device globals; no allocation allowed) ----------
__device__ __align__(128) __nv_bfloat16 g_hsb[MAXN * F128];   // GEMM outputs (pre-agg), bf16
__device__ __align__(128) __nv_bfloat16 g_accb[MAXN * F128];  // agg1 out (post-tanh), bf16 -> gemm2
__device__ __align__(128) float g_accf[MAXN * F128];          // agg2 out (post-tanh), fp32 -> final
__device__ __align__(128) __nv_bfloat16 g_W1b[F128 * F128];   // W1 bf16, smem-swizzled layout
__device__ __align__(128) __nv_bfloat16 g_Wcb[F128 * F128];   // Wl@W2 bf16, smem-swizzled layout
__device__ float g_bpre[F128];
__device__ int   g_indeg[MAXN];
__device__ int   g_off[MAXN];
__device__ int   g_cur[MAXN];
__device__ int   g_csr[MAXE];
__device__ int   g_bsum[256];
__device__ int   g_bex[256];

// ---------------- helpers ----------------
__device__ __forceinline__ float4 f4add(float4 a, float4 b) {
    return make_float4(a.x + b.x, a.y + b.y, a.z + b.z, a.w + b.w);
}

__device__ __forceinline__ void atomicMaxFloat(float* addr, float v) {
    if (v >= 0.0f) atomicMax((int*)addr, __float_as_int(v));
    else           atomicMin((unsigned int*)addr, __float_as_uint(v));
}

// pack 2 floats -> bf16x2
__device__ __forceinline__ unsigned cvt_bf2(float hi, float lo) {
    unsigned d;
    asm("cvt.rn.bf16x2.f32 %0, %1, %2;" : "=r"(d) : "f"(hi), "f"(lo));
    return d;
}

__device__ __forceinline__ float4 b2f4(uint2 u) {
    __nv_bfloat162 p0 = *reinterpret_cast<__nv_bfloat162*>(&u.x);
    __nv_bfloat162 p1 = *reinterpret_cast<__nv_bfloat162*>(&u.y);
    float2 f0 = __bfloat1622float2(p0);
    float2 f1 = __bfloat1622float2(p1);
    return make_float4(f0.x, f0.y, f1.x, f1.y);
}

__device__ __forceinline__ unsigned sm_u32(const void* p) {
    return (unsigned)__cvta_generic_to_shared(p);
}

#define LDSM_X4(r0, r1, r2, r3, addr) \
    asm volatile("ldmatrix.sync.aligned.m8n8.x4.shared.b16 {%0,%1,%2,%3}, [%4];" \
        : "=r"(r0), "=r"(r1), "=r"(r2), "=r"(r3) : "r"(addr))
#define LDSM_X4T(r0, r1, r2, r3, addr) \
    asm volatile("ldmatrix.sync.aligned.m8n8.x4.trans.shared.b16 {%0,%1,%2,%3}, [%4];" \
        : "=r"(r0), "=r"(r1), "=r"(r2), "=r"(r3) : "r"(addr))

__device__ __forceinline__ void mma_bf16(float* c, const unsigned* a, const unsigned* b) {
    asm("mma.sync.aligned.m16n8k16.row.col.f32.bf16.bf16.f32 "
        "{%0,%1,%2,%3}, {%4,%5,%6,%7}, {%8,%9}, {%0,%1,%2,%3};"
        : "+f"(c[0]), "+f"(c[1]), "+f"(c[2]), "+f"(c[3])
        : "r"(a[0]), "r"(a[1]), "r"(a[2]), "r"(a[3]), "r"(b[0]), "r"(b[1]));
}

#define CP_ASYNC16(dst, src) \
    asm volatile("cp.async.cg.shared.global [%0], [%1], 16;" :: "r"(dst), "l"(src))
#define CP_COMMIT() asm volatile("cp.async.commit_group;")
#define CP_WAIT0()  asm volatile("cp.async.wait_group 0;" ::: "memory")

// packed fp32x2 FMA (k_final)
#define FMA2(d, a, b) \
    asm("fma.rn.f32x2 %0, %1, %2, %0;" : "+l"(d) : "l"(a), "l"(b))
#define PACK2(d, lo, hi) \
    asm("mov.b64 %0, {%1, %2};" : "=l"(d) : "r"(__float_as_uint(lo)), "r"(__float_as_uint(hi)))
#define UNPACK2(lo, hi, d) \
    { unsigned int _l, _h; asm("mov.b64 {%0, %1}, %2;" : "=r"(_l), "=r"(_h) : "l"(d)); \
      lo = __uint_as_float(_l); hi = __uint_as_float(_h); }

// ---------------- preprocessing ----------------
__global__ void k_init_indeg(int N) {
    int n = blockIdx.x * blockDim.x + threadIdx.x;
    if (n < N) g_indeg[n] = 0;
}

__global__ void k_count(const int* __restrict__ ei, int E) {
    int e = blockIdx.x * blockDim.x + threadIdx.x;
    if (e < E) atomicAdd(&g_indeg[ei[E + e]], 1);
}

__global__ void k_scan_p1(int N) {
    int t = threadIdx.x;
    int n = blockIdx.x * 256 + t;
    int v = (n < N) ? g_indeg[n] : 0;
    #pragma unroll
    for (int o = 16; o > 0; o >>= 1) v += __shfl_down_sync(0xffffffffu, v, o);
    __shared__ int ws[8];
    if ((t & 31) == 0) ws[t >> 5] = v;
    __syncthreads();
    if (t < 8) {
        int s = ws[t];
        #pragma unroll
        for (int o = 4; o > 0; o >>= 1) s += __shfl_down_sync(0xffu, s, o);
        if (t == 0) g_bsum[blockIdx.x] = s;
    }
}

__global__ void k_scan_p2(int NB) {
    int t = threadIdx.x;
    int lane = t & 31, w = t >> 5;
    int v = (t < NB) ? g_bsum[t] : 0;
    int x = v;
    #pragma unroll
    for (int o = 1; o < 32; o <<= 1) {
        int y = __shfl_up_sync(0xffffffffu, x, o);
        if (lane >= o) x += y;
    }
    __shared__ int ws[8];
    if (lane == 31) ws[w] = x;
    __syncthreads();
    int wo = 0;
    #pragma unroll
    for (int j = 0; j < 8; j++) if (j < w) wo += ws[j];
    g_bex[t] = x - v + wo;
}

__global__ void k_scan_p3(int N) {
    int t = threadIdx.x;
    int n = blockIdx.x * 256 + t;
    int lane = t & 31, w = t >> 5;
    int deg = (n < N) ? g_indeg[n] : 0;
    int x = deg;
    #pragma unroll
    for (int o = 1; o < 32; o <<= 1) {
        int y = __shfl_up_sync(0xffffffffu, x, o);
        if (lane >= o) x += y;
    }
    __shared__ int ws[8];
    if (lane == 31) ws[w] = x;
    __syncthreads();
    int wo = 0;
    #pragma unroll
    for (int j = 0; j < 8; j++) if (j < w) wo += ws[j];
    int ex = x - deg + wo + g_bex[blockIdx.x];
    if (n < N) { g_off[n] = ex; g_cur[n] = ex; }
}

__global__ void k_fill(const int* __restrict__ ei, int E) {
    int e = blockIdx.x * blockDim.x + threadIdx.x;
    if (e < E) {
        int src = ei[e];
        int dst = ei[E + e];
        int p = atomicAdd(&g_cur[dst], 1);
        g_csr[p] = src;
    }
}

// ------- weight prep: Wc=Wl@W2 -> bf16 swizzled; W1 -> bf16 swizzled; bpre; out init
__device__ __forceinline__ void store_swz(__nv_bfloat16* base, int k, int c, float v) {
    int idx = k * 128 + ((((c >> 3) ^ (k & 7)) << 3) | (c & 7));
    base[idx] = __float2bfloat16(v);
}

__global__ void k_wc(const float* __restrict__ Wl, const float* __restrict__ bl,
                     const float* __restrict__ W2, const float* __restrict__ W1,
                     float* __restrict__ out) {
    int idx = blockIdx.x * blockDim.x + threadIdx.x;
    if (idx < F128 * F128) {
        int r = idx >> 7, c = idx & 127;
        float s = 0.0f;
        #pragma unroll 8
        for (int k = 0; k < F128; k++) s += Wl[r * F128 + k] * W2[k * F128 + c];
        store_swz(g_Wcb, r, c, s);
        store_swz(g_W1b, r, c, W1[idx]);
    }
    if (idx < F128) {
        float s = 0.0f;
        #pragma unroll 8
        for (int k = 0; k < F128; k++) s += bl[k] * W2[k * F128 + idx];
        g_bpre[idx] = s;
    }
    if (idx < 64) out[idx] = -INFINITY;
}

// ============== bf16 MMA GEMM: 64(M)x128(N)xK128, 8 warps ==================
// sA: bf16 [m=64][k chunks], pitch 256B, chunk c ^ (m&7)   (16 KB)
// sB: bf16 [k=128][n chunks], pitch 256B, chunk c ^ (k&7) (pre-swizzled, 32 KB)
// Warp w: wm=w&1 -> rows wm*32..+31 (2 m16 tiles); wn=w>>1 -> cols wn*32..+31

__device__ __forceinline__ void mma_loop64(const char* sA, const char* sB,
                                           int lane, int wm, int wn, float c[2][4][4]) {
    int tl = lane >> 3, li = lane & 7;
    unsigned aBase = sm_u32(sA) + (unsigned)((wm * 32 + li + (tl & 1) * 8) * 256);
    int thA = tl >> 1;
    int klB = li + (tl & 1) * 8;
    int nch0 = wn * 4 + (tl >> 1);
    unsigned bBase0 = sm_u32(sB) + (unsigned)(klB * 256 + ((nch0 ^ (klB & 7)) << 4));
    unsigned bBase1 = sm_u32(sB) + (unsigned)(klB * 256 + (((nch0 + 2) ^ (klB & 7)) << 4));
    #pragma unroll
    for (int s = 0; s < 8; s++) {
        unsigned a[2][4], b[4][2];
        unsigned ach = (unsigned)((((2 * s + thA) ^ li)) << 4);
        #pragma unroll
        for (int mt = 0; mt < 2; mt++)
            LDSM_X4(a[mt][0], a[mt][1], a[mt][2], a[mt][3],
                    aBase + (unsigned)(mt * 16 * 256) + ach);
        LDSM_X4T(b[0][0], b[0][1], b[1][0], b[1][1], bBase0 + (unsigned)(s * 4096));
        LDSM_X4T(b[2][0], b[2][1], b[3][0], b[3][1], bBase1 + (unsigned)(s * 4096));
        #pragma unroll
        for (int mt = 0; mt < 2; mt++)
            #pragma unroll
            for (int nt = 0; nt < 4; nt++)
                mma_bf16(c[mt][nt], a[mt], b[nt]);
    }
}

// ---------------- GEMM 1: hsb = bf16( (x @ W1) * dinv[row] ) ---------------
__global__ __launch_bounds__(256, 3) void k_gemm1(const float* __restrict__ A, int N) {
    extern __shared__ __align__(16) char smem[];
    char* sA = smem;             // 16 KB
    char* sB = smem + 16384;     // 32 KB
    int tid = threadIdx.x;
    int lane = tid & 31, w = tid >> 5;
    int wm = w & 1, wn = w >> 1;
    int q = lane >> 2, t = lane & 3;
    int row0 = blockIdx.x * 64;
    float c[2][4][4] = {};

    // stage B: raw 16B copies from pre-swizzled g_W1b (contiguous, coalesced)
    {
        unsigned dst = sm_u32(sB) + (unsigned)(tid * 128);
        const char* src = (const char*)g_W1b + tid * 128;
        #pragma unroll
        for (int i = 0; i < 8; i++) CP_ASYNC16(dst + i * 16, src + i * 16);
        CP_COMMIT();
    }
    // stage A COALESCED: each warp reads whole rows (512B = 32 lanes x float4)
    {
        #pragma unroll
        for (int i = 0; i < 8; i++) {
            int r = w * 8 + i;
            int gr = row0 + r;
            float4 v = make_float4(0, 0, 0, 0);
            if (gr < N) v = *(const float4*)(A + gr * 128 + lane * 4);
            uint2 u;
            u.x = cvt_bf2(v.y, v.x);
            u.y = cvt_bf2(v.w, v.z);
            int ch = lane >> 1;
            *(uint2*)(sA + r * 256 + ((ch ^ (r & 7)) << 4) + ((lane & 1) << 3)) = u;
        }
    }
    CP_WAIT0();
    __syncthreads();

    mma_loop64(sA, sB, lane, wm, wn, c);

    #pragma unroll
    for (int mt = 0; mt < 2; mt++) {
        #pragma unroll
        for (int half = 0; half < 2; half++) {
            int r = row0 + wm * 32 + mt * 16 + q + half * 8;
            if (r < N) {
                float dv = rsqrtf((float)(g_indeg[r] + 1));
                #pragma unroll
                for (int nt = 0; nt < 4; nt++) {
                    int col = wn * 32 + nt * 8 + 2 * t;
                    *(unsigned*)(&g_hsb[r * 128 + col]) =
                        cvt_bf2(c[mt][nt][half * 2 + 1] * dv, c[mt][nt][half * 2] * dv);
                }
            }
        }
    }
}

// ------- GEMM 2: hsb = bf16( (accb @ Wc + bpre) * dinv )  (A already tanh'd)
__global__ __launch_bounds__(256, 3) void k_gemm2(int N) {
    extern __shared__ __align__(16) char smem[];
    char* sA = smem;
    char* sB = smem + 16384;
    int tid = threadIdx.x;
    int lane = tid & 31, w = tid >> 5;
    int wm = w & 1, wn = w >> 1;
    int q = lane >> 2, t = lane & 3;
    int row0 = blockIdx.x * 64;
    float c[2][4][4] = {};

    {
        unsigned dst = sm_u32(sB) + (unsigned)(tid * 128);
        const char* src = (const char*)g_Wcb + tid * 128;
        #pragma unroll
        for (int i = 0; i < 8; i++) CP_ASYNC16(dst + i * 16, src + i * 16);
    }
    // stage A COALESCED: warp handles 2 adjacent bf16 rows per instr (512B)
    {
        #pragma unroll
        for (int i = 0; i < 4; i++) {
            int r = w * 8 + i * 2 + (lane >> 4);
            int gr = row0 + r;
            int ch = lane & 15;
            unsigned dst = sm_u32(sA) + (unsigned)(r * 256 + ((ch ^ (r & 7)) << 4));
            if (gr < N) {
                CP_ASYNC16(dst, (const char*)g_accb + gr * 256 + ch * 16);
            } else {
                *(uint4*)(sA + r * 256 + ((ch ^ (r & 7)) << 4)) = make_uint4(0, 0, 0, 0);
            }
        }
    }
    CP_COMMIT();
    CP_WAIT0();
    __syncthreads();

    mma_loop64(sA, sB, lane, wm, wn, c);

    #pragma unroll
    for (int mt = 0; mt < 2; mt++) {
        #pragma unroll
        for (int half = 0; half < 2; half++) {
            int r = row0 + wm * 32 + mt * 16 + q + half * 8;
            if (r < N) {
                float dv = rsqrtf((float)(g_indeg[r] + 1));
                #pragma unroll
                for (int nt = 0; nt < 4; nt++) {
                    int col = wn * 32 + nt * 8 + 2 * t;
                    float2 bp = *(const float2*)(g_bpre + col);
                    *(unsigned*)(&g_hsb[r * 128 + col]) =
                        cvt_bf2((c[mt][nt][half * 2 + 1] + bp.y) * dv,
                                (c[mt][nt][half * 2] + bp.x) * dv);
                }
            }
        }
    }
}

// -------- Aggregation + fused epilogue (fp32 tanh):
//   out[n] = tanh( dinv[n] * (hsb[n] + sum_{in} hsb[src]) + bias )
// WRITE_F32=false -> bf16 g_accb (feeds bf16-MMA gemm2; quantized there anyway)
// WRITE_F32=true  -> fp32 g_accf (feeds fp32 final GEMM; keeps last layer exact)
template <bool WRITE_F32>
__global__ void k_agg(const float* __restrict__ bias, int N) {
    int gw = (blockIdx.x * blockDim.x + threadIdx.x) >> 5;
    int lane = threadIdx.x & 31;
    if (gw >= N) return;
    const uint2* hsb = (const uint2*)g_hsb;
    int beg = g_off[gw];
    int cnt = g_indeg[gw];
    float4 s = b2f4(hsb[gw * 32 + lane]);
    int j = 0;
    for (; j + 4 <= cnt; j += 4) {
        int s0 = g_csr[beg + j];
        int s1 = g_csr[beg + j + 1];
        int s2 = g_csr[beg + j + 2];
        int s3 = g_csr[beg + j + 3];
        float4 a = b2f4(hsb[s0 * 32 + lane]);
        float4 b = b2f4(hsb[s1 * 32 + lane]);
        float4 c = b2f4(hsb[s2 * 32 + lane]);
        float4 d = b2f4(hsb[s3 * 32 + lane]);
        s = f4add(s, f4add(f4add(a, b), f4add(c, d)));
    }
    for (; j < cnt; j++) s = f4add(s, b2f4(hsb[g_csr[beg + j] * 32 + lane]));
    float dv = rsqrtf((float)(cnt + 1));
    float4 bb = *(const float4*)(bias + lane * 4);
    float z0 = tanhf(fmaf(dv, s.x, bb.x));
    float z1 = tanhf(fmaf(dv, s.y, bb.y));
    float z2 = tanhf(fmaf(dv, s.z, bb.z));
    float z3 = tanhf(fmaf(dv, s.w, bb.w));
    if (WRITE_F32) {
        ((float4*)g_accf)[gw * 32 + lane] = make_float4(z0, z1, z2, z3);
    } else {
        ((uint2*)g_accb)[gw * 32 + lane] = make_uint2(cvt_bf2(z1, z0), cvt_bf2(z3, z2));
    }
}

// ---------------- Final: out = max_n( accf @ Wo + bo )  (fp32 FFMA2) -------
__global__ void k_final(const float* __restrict__ Wo, const float* __restrict__ bo,
                        float* __restrict__ out, int N) {
    __shared__ float As[32 * 64];
    __shared__ float Bs[32 * 64];
    int tid = threadIdx.x;
    int tc = tid & 31, tr = tid >> 5;
    int row0 = blockIdx.x * 64;
    unsigned long long acc2[4][2] = {};

    int lr = tid & 63;
    int kc = (tid >> 6) * 8;
    int gr = row0 + lr;

    for (int k0 = 0; k0 < 128; k0 += 32) {
        {
            float4 v0 = make_float4(0, 0, 0, 0), v1 = make_float4(0, 0, 0, 0);
            if (gr < N) {
                v0 = *(const float4*)(g_accf + gr * 128 + k0 + kc);
                v1 = *(const float4*)(g_accf + gr * 128 + k0 + kc + 4);
            }
            As[(kc + 0) * 64 + lr] = v0.x; As[(kc + 1) * 64 + lr] = v0.y;
            As[(kc + 2) * 64 + lr] = v0.z; As[(kc + 3) * 64 + lr] = v0.w;
            As[(kc + 4) * 64 + lr] = v1.x; As[(kc + 5) * 64 + lr] = v1.y;
            As[(kc + 6) * 64 + lr] = v1.z; As[(kc + 7) * 64 + lr] = v1.w;
        }
        {
            const float4* Bg = (const float4*)(Wo + k0 * 64);
            float4* Bs4 = (float4*)Bs;
            Bs4[tid] = Bg[tid];
            Bs4[tid + 256] = Bg[tid + 256];
        }
        __syncthreads();
        #pragma unroll
        for (int k = 0; k < 32; k++) {
            float2 b2v = *(const float2*)(Bs + k * 64 + tc * 2);
            unsigned long long bb[2];
            PACK2(bb[0], b2v.x, b2v.x); PACK2(bb[1], b2v.y, b2v.y);
            #pragma unroll
            for (int i2 = 0; i2 < 4; i2++) {
                unsigned long long ap = *(const unsigned long long*)(As + k * 64 + tr * 8 + 2 * i2);
                FMA2(acc2[i2][0], ap, bb[0]);
                FMA2(acc2[i2][1], ap, bb[1]);
            }
        }
        __syncthreads();
    }
    float bo0 = bo[tc * 2], bo1 = bo[tc * 2 + 1];
    float m0 = -INFINITY, m1 = -INFINITY;
    #pragma unroll
    for (int i2 = 0; i2 < 4; i2++) {
        float lo0, hi0, lo1, hi1;
        UNPACK2(lo0, hi0, acc2[i2][0]);
        UNPACK2(lo1, hi1, acc2[i2][1]);
        int r0 = row0 + tr * 8 + 2 * i2;
        if (r0 < N)     { m0 = fmaxf(m0, lo0 + bo0); m1 = fmaxf(m1, lo1 + bo1); }
        if (r0 + 1 < N) { m0 = fmaxf(m0, hi0 + bo0); m1 = fmaxf(m1, hi1 + bo1); }
    }
    As[tr * 64 + tc * 2] = m0;
    As[tr * 64 + tc * 2 + 1] = m1;
    __syncthreads();
    if (tid < 64) {
        float m = As[tid];
        #pragma unroll
        for (int j = 1; j < 8; j++) m = fmaxf(m, As[j * 64 + tid]);
        atomicMaxFloat(&out[tid], m);
    }
}

// ---------------- launch ----------------
extern "C" void kernel_launch(void* const* d_in, const int* in_sizes, int n_in,
                              void* d_out, int out_size) {
    const float* x  = (const float*)d_in[0];
    const int*   ei = (const int*)d_in[1];
    const float* W1 = (const float*)d_in[2];
    const float* b1 = (const float*)d_in[3];
    const float* Wl = (const float*)d_in[4];
    const float* bl = (const float*)d_in[5];
    const float* W2 = (const float*)d_in[6];
    const float* b2 = (const float*)d_in[7];
    const float* Wo = (const float*)d_in[8];
    const float* bo = (const float*)d_in[9];
    float* out = (float*)d_out;

    int N = in_sizes[0] / F128;   // 50000
    int E = in_sizes[1] / 2;      // 800000

    int nbN = (N + 255) / 256;
    int nbE = (E + 255) / 256;
    int nbG = (N + 63) / 64;      // 782 (MMA gemms, 64-row tiles)
    int nbF = (N + 63) / 64;      // 782 (final)
    int nbA = (N + 7) / 8;        // 6250

    static const int SMEM = 49152;   // 16 KB sA + 32 KB sB
    cudaFuncSetAttribute(k_gemm1, cudaFuncAttributeMaxDynamicSharedMemorySize, SMEM);
    cudaFuncSetAttribute(k_gemm2, cudaFuncAttributeMaxDynamicSharedMemorySize, SMEM);

    // launch #4 = k_gemm1 (profiled by ncu)
    k_init_indeg<<<nbN, 256>>>(N);                       // 1
    k_wc<<<64, 256>>>(Wl, bl, W2, W1, out);              // 2
    k_count<<<nbE, 256>>>(ei, E);                        // 3
    k_gemm1<<<nbG, 256, SMEM>>>(x, N);                   // 4  <- profiled
    k_scan_p1<<<nbN, 256>>>(N);                          // 5
    k_scan_p2<<<1, 256>>>(nbN);                          // 6
    k_scan_p3<<<nbN, 256>>>(N);                          // 7
    k_fill<<<nbE, 256>>>(ei, E);                         // 8
    k_agg<false><<<nbA, 256>>>(b1, N);                   // 9   -> bf16 for gemm2
    k_gemm2<<<nbG, 256, SMEM>>>(N);                      // 10
    k_agg<true><<<nbA, 256>>>(b2, N);                    // 11  -> fp32 for final
    k_final<<<nbF, 256>>>(Wo, bo, out, N);               // 12
}